// round 15
// baseline (speedup 1.0000x reference)
#include <cuda_runtime.h>
#include <cuda_bf16.h>

#define N_PROP 65536
#define N_TGT  128
#define KTOP   8
#define KCAND  16
#define NSEG   8
#define SEGLEN (N_PROP / NSEG)   // 8192

typedef unsigned int u32;

// Scratch (static __device__ — no allocations allowed)
__device__ float g_scores[(size_t)N_PROP * N_TGT];    // n-major flat keys
__device__ float g_seg_val[N_TGT * NSEG * KCAND];
__device__ int   g_seg_idx[N_TGT * NSEG * KCAND];
__device__ int   g_cand_idx[N_TGT * KCAND];
__device__ float g_top_val[N_TGT * KTOP];
__device__ int   g_top_idx[N_TGT * KTOP];

// pack two f32 -> bf16x2 (lo = second arg)
static __device__ __forceinline__ u32 bfpair(float hi, float lo) {
    u32 d;
    asm("cvt.rn.bf16x2.f32 %0, %1, %2;" : "=r"(d) : "f"(hi), "f"(lo));
    return d;
}

static __device__ __forceinline__ void mma_k8(float c[4], u32 a0, u32 a1, u32 b0) {
    asm volatile(
        "mma.sync.aligned.m16n8k8.row.col.f32.bf16.bf16.f32 "
        "{%0,%1,%2,%3}, {%4,%5}, {%6}, {%0,%1,%2,%3};"
        : "+f"(c[0]), "+f"(c[1]), "+f"(c[2]), "+f"(c[3])
        : "r"(a0), "r"(a1), "r"(b0));
}
static __device__ __forceinline__ void mma_k16(float c[4], const u32 a[4],
                                               u32 b0, u32 b1) {
    asm volatile(
        "mma.sync.aligned.m16n8k16.row.col.f32.bf16.bf16.f32 "
        "{%0,%1,%2,%3}, {%4,%5,%6,%7}, {%8,%9}, {%0,%1,%2,%3};"
        : "+f"(c[0]), "+f"(c[1]), "+f"(c[2]), "+f"(c[3])
        : "r"(a[0]), "r"(a[1]), "r"(a[2]), "r"(a[3]), "r"(b0), "r"(b1));
}

// ---------------------------------------------------------------------------
// Phase A: warp-level HMMA approximate scoring, 2 tiles (32 rows) per warp
// iteration. Rows = flat (n,t): row = n*128 + t. Stores are n-major flat
// (fully coalesced; the 32 rows of an iteration are consecutive).
// key = logit>=0 ? logit : -1  (approx; exact re-ranking in phase B)
// ---------------------------------------------------------------------------
__global__ __launch_bounds__(128) void score_mma_kernel(
    const float* __restrict__ th, const float* __restrict__ xy,
    const float* __restrict__ di, const float* __restrict__ po,
    const float* __restrict__ ne, const float* __restrict__ io,
    const float* __restrict__ W1, const float* __restrict__ b1,
    const float* __restrict__ W2, const float* __restrict__ b2,
    const float* __restrict__ W3, const float* __restrict__ b3)
{
    const int lane = threadIdx.x & 31;
    const int grp  = lane >> 2;       // 0..7  (row within tile; +8 for upper)
    const int qid  = lane & 3;        // 0..3  (K/N column group)

    const int warps_per_blk = blockDim.x >> 5;
    const int gwarp  = blockIdx.x * warps_per_blk + (threadIdx.x >> 5);
    const int nwarp  = gridDim.x * warps_per_blk;
    const int npairs = (N_PROP * N_TGT) / 32;   // 2 tiles per iteration

    // ---- W1 B-fragments (k8) ----
    u32 bw1[8];
    {
        const int k0 = 2 * qid;
        #pragma unroll
        for (int jt = 0; jt < 8; jt++) {
            const int n = 8 * jt + grp;
            float lo = (k0 == 6) ? b1[n] : W1[k0 * 64 + n];
            float hi = (k0 + 1 == 7) ? 0.0f : W1[(k0 + 1) * 64 + n];
            bw1[jt] = bfpair(hi, lo);
        }
    }

    // ---- W2 B-fragments (k16): [kt][nt] ----
    u32 bw2[4][4][2];
    {
        #pragma unroll
        for (int kt = 0; kt < 4; kt++) {
            const int k0 = 16 * kt + 2 * qid;
            #pragma unroll
            for (int nt = 0; nt < 4; nt++) {
                const int n = 8 * nt + grp;
                bw2[kt][nt][0] = bfpair(W2[(k0 + 1) * 32 + n], W2[k0 * 32 + n]);
                bw2[kt][nt][1] = bfpair(W2[(k0 + 9) * 32 + n], W2[(k0 + 8) * 32 + n]);
            }
        }
    }

    // ---- L3 per-lane constants ----
    float w3v[4][2], b2v[4][2];
    #pragma unroll
    for (int nt = 0; nt < 4; nt++) {
        #pragma unroll
        for (int e = 0; e < 2; e++) {
            const int c = 8 * nt + 2 * qid + e;
            w3v[nt][e] = W3[c];
            b2v[nt][e] = b2[c];
        }
    }
    const float b3v = b3[0];

    // per-lane feature sources: features 2*qid and 2*qid+1
    const float* pA = (qid == 0) ? th : (qid == 1) ? di : ne;   // qid3: dummy
    const float* pB = (qid == 0) ? xy : (qid == 1) ? po : io;
    const float capA = (qid == 0) ? 180.0f : (qid == 1) ? 800.0f : 0.0f;
    const float capB = (qid == 0) ? 800.0f : 0.0f;
    const float invA = (qid == 0) ? (1.0f / 180.0f) : (1.0f / 800.0f);
    const float invB = 1.0f / 800.0f;

    for (int pair = gwarp; pair < npairs; pair += nwarp) {
        const int row0 = pair * 32 + grp;     // tile0: rows row0, row0+8
        const int row1 = row0 + 16;           // tile1: rows row1, row1+8

        // ---- A-fragments for L1 (k8) for both tiles ----
        u32 a0, a1, c0, c1;
        if (qid == 3) {
            a0 = 0x00003F80u; a1 = 0x00003F80u;   // (col6=1.0 bias, col7=0)
            c0 = 0x00003F80u; c1 = 0x00003F80u;
        } else {
            float vA0 = pA[row0],      vB0 = pB[row0];
            float vA8 = pA[row0 + 8],  vB8 = pB[row0 + 8];
            float vC0 = pA[row1],      vD0 = pB[row1];
            float vC8 = pA[row1 + 8],  vD8 = pB[row1 + 8];
            float fA0 = (capA > 0.0f) ? 1.0f - fminf(vA0, capA) * invA : vA0;
            float fA8 = (capA > 0.0f) ? 1.0f - fminf(vA8, capA) * invA : vA8;
            float fC0 = (capA > 0.0f) ? 1.0f - fminf(vC0, capA) * invA : vC0;
            float fC8 = (capA > 0.0f) ? 1.0f - fminf(vC8, capA) * invA : vC8;
            float fB0 = (capB > 0.0f) ? 1.0f - fminf(vB0, capB) * invB : vB0;
            float fB8 = (capB > 0.0f) ? 1.0f - fminf(vB8, capB) * invB : vB8;
            float fD0 = (capB > 0.0f) ? 1.0f - fminf(vD0, capB) * invB : vD0;
            float fD8 = (capB > 0.0f) ? 1.0f - fminf(vD8, capB) * invB : vD8;
            a0 = bfpair(fB0, fA0);
            a1 = bfpair(fB8, fA8);
            c0 = bfpair(fD0, fC0);
            c1 = bfpair(fD8, fC8);
        }

        // ---- L1 tile0 -> compressed A-frags ----
        u32 aF0[4][4], aF1[4][4];
        {
            float h1[8][4];
            #pragma unroll
            for (int jt = 0; jt < 8; jt++) {
                h1[jt][0] = 0.0f; h1[jt][1] = 0.0f; h1[jt][2] = 0.0f; h1[jt][3] = 0.0f;
                mma_k8(h1[jt], a0, a1, bw1[jt]);
            }
            #pragma unroll
            for (int kt = 0; kt < 4; kt++) {
                aF0[kt][0] = bfpair(fmaxf(h1[2*kt][1], 0.0f),   fmaxf(h1[2*kt][0], 0.0f));
                aF0[kt][1] = bfpair(fmaxf(h1[2*kt][3], 0.0f),   fmaxf(h1[2*kt][2], 0.0f));
                aF0[kt][2] = bfpair(fmaxf(h1[2*kt+1][1], 0.0f), fmaxf(h1[2*kt+1][0], 0.0f));
                aF0[kt][3] = bfpair(fmaxf(h1[2*kt+1][3], 0.0f), fmaxf(h1[2*kt+1][2], 0.0f));
            }
        }
        // ---- L1 tile1 ----
        {
            float h1[8][4];
            #pragma unroll
            for (int jt = 0; jt < 8; jt++) {
                h1[jt][0] = 0.0f; h1[jt][1] = 0.0f; h1[jt][2] = 0.0f; h1[jt][3] = 0.0f;
                mma_k8(h1[jt], c0, c1, bw1[jt]);
            }
            #pragma unroll
            for (int kt = 0; kt < 4; kt++) {
                aF1[kt][0] = bfpair(fmaxf(h1[2*kt][1], 0.0f),   fmaxf(h1[2*kt][0], 0.0f));
                aF1[kt][1] = bfpair(fmaxf(h1[2*kt][3], 0.0f),   fmaxf(h1[2*kt][2], 0.0f));
                aF1[kt][2] = bfpair(fmaxf(h1[2*kt+1][1], 0.0f), fmaxf(h1[2*kt+1][0], 0.0f));
                aF1[kt][3] = bfpair(fmaxf(h1[2*kt+1][3], 0.0f), fmaxf(h1[2*kt+1][2], 0.0f));
            }
        }

        // ---- L2: two independent chains, b2 folded into C ----
        float h2a[4][4], h2b[4][4];
        #pragma unroll
        for (int nt = 0; nt < 4; nt++) {
            h2a[nt][0] = b2v[nt][0]; h2a[nt][1] = b2v[nt][1];
            h2a[nt][2] = b2v[nt][0]; h2a[nt][3] = b2v[nt][1];
            h2b[nt][0] = b2v[nt][0]; h2b[nt][1] = b2v[nt][1];
            h2b[nt][2] = b2v[nt][0]; h2b[nt][3] = b2v[nt][1];
        }
        #pragma unroll
        for (int kt = 0; kt < 4; kt++) {
            #pragma unroll
            for (int nt = 0; nt < 4; nt++) {
                mma_k16(h2a[nt], aF0[kt], bw2[kt][nt][0], bw2[kt][nt][1]);
                mma_k16(h2b[nt], aF1[kt], bw2[kt][nt][0], bw2[kt][nt][1]);
            }
        }

        // ---- L3: relu(H2) . W3, quad reduction; two tiles interleaved ----
        float p0 = 0.0f, p8 = 0.0f, q0 = 0.0f, q8 = 0.0f;
        #pragma unroll
        for (int nt = 0; nt < 4; nt++) {
            #pragma unroll
            for (int e = 0; e < 2; e++) {
                p0 = fmaf(fmaxf(h2a[nt][e],     0.0f), w3v[nt][e], p0);
                p8 = fmaf(fmaxf(h2a[nt][2 + e], 0.0f), w3v[nt][e], p8);
                q0 = fmaf(fmaxf(h2b[nt][e],     0.0f), w3v[nt][e], q0);
                q8 = fmaf(fmaxf(h2b[nt][2 + e], 0.0f), w3v[nt][e], q8);
            }
        }
        p0 += __shfl_xor_sync(0xFFFFFFFFu, p0, 1);
        p8 += __shfl_xor_sync(0xFFFFFFFFu, p8, 1);
        q0 += __shfl_xor_sync(0xFFFFFFFFu, q0, 1);
        q8 += __shfl_xor_sync(0xFFFFFFFFu, q8, 1);
        p0 += __shfl_xor_sync(0xFFFFFFFFu, p0, 2);
        p8 += __shfl_xor_sync(0xFFFFFFFFu, p8, 2);
        q0 += __shfl_xor_sync(0xFFFFFFFFu, q0, 2);
        q8 += __shfl_xor_sync(0xFFFFFFFFu, q8, 2);

        if (qid == 0) {
            const float l0 = p0 + b3v, l8 = p8 + b3v;
            const float m0 = q0 + b3v, m8 = q8 + b3v;
            g_scores[row0]      = (l0 >= 0.0f) ? l0 : -1.0f;   // coalesced n-major
            g_scores[row0 + 8]  = (l8 >= 0.0f) ? l8 : -1.0f;
            g_scores[row1]      = (m0 >= 0.0f) ? m0 : -1.0f;
            g_scores[row1 + 8]  = (m8 >= 0.0f) ? m8 : -1.0f;
        }
    }
}

// ---------------------------------------------------------------------------
// Topk stage 1: per-(target, segment) top-16 over 8192 proposals.
// grid = N_TGT * NSEG blocks, 256 threads. Column reads are strided 512B but
// line-shared across the 128 target-blocks via L2.
// ---------------------------------------------------------------------------
__global__ __launch_bounds__(256) void topk_seg_kernel()
{
    __shared__ float sval[256 * KCAND];
    __shared__ int   sidx[256 * KCAND];

    const int t    = blockIdx.x >> 3;
    const int seg  = blockIdx.x & (NSEG - 1);
    const int tid  = threadIdx.x;
    const int base = seg * SEGLEN;

    float val[KCAND];
    int   idx[KCAND];
    #pragma unroll
    for (int k = 0; k < KCAND; k++) { val[k] = -3.4e38f; idx[k] = 0x7fffffff; }

    // ascending-n per thread; strict > keeps earliest index on ties
    #pragma unroll 4
    for (int k = 0; k < SEGLEN / 256; k++) {
        const int n = base + tid + k * 256;
        const float v = g_scores[(size_t)n * N_TGT + t];
        if (v > val[KCAND - 1]) {
            val[KCAND - 1] = v; idx[KCAND - 1] = n;
            #pragma unroll
            for (int p = KCAND - 1; p > 0; p--) {
                if (val[p] > val[p - 1]) {
                    float tv = val[p]; val[p] = val[p - 1]; val[p - 1] = tv;
                    int   ti = idx[p]; idx[p] = idx[p - 1]; idx[p - 1] = ti;
                }
            }
        }
    }

    #pragma unroll
    for (int k = 0; k < KCAND; k++) { sval[tid * KCAND + k] = val[k]; sidx[tid * KCAND + k] = idx[k]; }
    __syncthreads();

    for (int s = 128; s > 0; s >>= 1) {
        float mv[KCAND]; int mi[KCAND];
        if (tid < s) {
            const float* av = &sval[tid * KCAND];
            const int*   ai = &sidx[tid * KCAND];
            const float* bv = &sval[(tid + s) * KCAND];
            const int*   bi = &sidx[(tid + s) * KCAND];
            int i = 0, j = 0;
            #pragma unroll
            for (int k = 0; k < KCAND; k++) {
                const float va = av[i], vb = bv[j];
                const int   ia = ai[i], ib = bi[j];
                const bool take_a = (va > vb) || (va == vb && ia < ib);
                if (take_a) { mv[k] = va; mi[k] = ia; i++; }
                else        { mv[k] = vb; mi[k] = ib; j++; }
            }
            #pragma unroll
            for (int k = 0; k < KCAND; k++) { sval[tid * KCAND + k] = mv[k]; sidx[tid * KCAND + k] = mi[k]; }
        }
        __syncthreads();
    }

    if (tid < KCAND) {
        g_seg_val[(t * NSEG + seg) * KCAND + tid] = sval[tid];
        g_seg_idx[(t * NSEG + seg) * KCAND + tid] = sidx[tid];
    }
}

// ---------------------------------------------------------------------------
// Topk stage 2: merge NSEG sorted 16-lists per target -> top-16 candidates.
// ---------------------------------------------------------------------------
__global__ __launch_bounds__(32) void topk_merge_kernel()
{
    __shared__ float sval[NSEG * KCAND];
    __shared__ int   sidx[NSEG * KCAND];

    const int t   = blockIdx.x;
    const int tid = threadIdx.x;

    for (int x = tid; x < NSEG * KCAND; x += 32) {
        sval[x] = g_seg_val[t * NSEG * KCAND + x];
        sidx[x] = g_seg_idx[t * NSEG * KCAND + x];
    }
    __syncwarp();

    for (int s = NSEG / 2; s > 0; s >>= 1) {
        float mv[KCAND]; int mi[KCAND];
        if (tid < s) {
            const float* av = &sval[tid * KCAND];
            const int*   ai = &sidx[tid * KCAND];
            const float* bv = &sval[(tid + s) * KCAND];
            const int*   bi = &sidx[(tid + s) * KCAND];
            int i = 0, j = 0;
            #pragma unroll
            for (int k = 0; k < KCAND; k++) {
                const float va = av[i], vb = bv[j];
                const int   ia = ai[i], ib = bi[j];
                const bool take_a = (va > vb) || (va == vb && ia < ib);
                if (take_a) { mv[k] = va; mi[k] = ia; i++; }
                else        { mv[k] = vb; mi[k] = ib; j++; }
            }
            #pragma unroll
            for (int k = 0; k < KCAND; k++) { sval[tid * KCAND + k] = mv[k]; sidx[tid * KCAND + k] = mi[k]; }
        }
        __syncwarp();
    }

    if (tid < KCAND)
        g_cand_idx[t * KCAND + tid] = sidx[tid];
}

// ---------------------------------------------------------------------------
// Phase B: exact fp32 rescoring of the 16 candidates per target, exact top-8.
// ---------------------------------------------------------------------------
__global__ __launch_bounds__(32) void rescore_kernel(
    const float* __restrict__ th, const float* __restrict__ xy,
    const float* __restrict__ di, const float* __restrict__ po,
    const float* __restrict__ ne, const float* __restrict__ io,
    const float* __restrict__ W1, const float* __restrict__ b1,
    const float* __restrict__ W2, const float* __restrict__ b2,
    const float* __restrict__ W3, const float* __restrict__ b3)
{
    __shared__ float skv[KCAND];
    __shared__ int   ski[KCAND];

    const int t   = blockIdx.x;
    const int tid = threadIdx.x;

    if (tid < KCAND) {
        const int n   = g_cand_idx[t * KCAND + tid];
        const int off = n * N_TGT + t;
        float f[6];
        f[0] = 1.0f - fminf(th[off], 180.0f) * (1.0f / 180.0f);
        f[1] = 1.0f - fminf(xy[off], 800.0f) * (1.0f / 800.0f);
        f[2] = 1.0f - fminf(di[off], 800.0f) * (1.0f / 800.0f);
        f[3] = po[off];
        f[4] = ne[off];
        f[5] = io[off];

        float h2[32];
        #pragma unroll
        for (int j = 0; j < 32; j++) h2[j] = b2[j];

        for (int i = 0; i < 64; i++) {
            float h = b1[i];
            #pragma unroll
            for (int k = 0; k < 6; k++) h = fmaf(f[k], W1[k * 64 + i], h);
            h = fmaxf(h, 0.0f);
            #pragma unroll
            for (int j = 0; j < 32; j++) h2[j] = fmaf(h, W2[i * 32 + j], h2[j]);
        }
        float acc = b3[0];
        #pragma unroll
        for (int j = 0; j < 32; j++)
            acc = fmaf(fmaxf(h2[j], 0.0f), W3[j], acc);

        skv[tid] = (acc >= 0.0f) ? acc : -1.0f;
        ski[tid] = n;
    }
    __syncthreads();

    if (tid == 0) {
        bool used[KCAND];
        #pragma unroll
        for (int k = 0; k < KCAND; k++) used[k] = false;
        for (int k = 0; k < KTOP; k++) {
            int best = -1;
            float bv = -3.4e38f; int bi = 0x7fffffff;
            for (int c = 0; c < KCAND; c++) {
                if (used[c]) continue;
                const float v = skv[c]; const int n = ski[c];
                if (v > bv || (v == bv && n < bi)) { bv = v; bi = n; best = c; }
            }
            used[best] = true;
            g_top_val[t * KTOP + k] = bv;
            g_top_idx[t * KTOP + k] = bi;
        }
    }
}

// ---------------------------------------------------------------------------
// Final: stable descending rank of targets[:,1], scatter output as float32.
// out = [rows(1024) | cols(1024) | valid(1024)].
// ---------------------------------------------------------------------------
__global__ __launch_bounds__(N_TGT) void assemble_kernel(
    const float* __restrict__ targets, float* __restrict__ out)
{
    __shared__ float key[N_TGT];
    const int t = threadIdx.x;
    key[t] = targets[t * 4 + 1];
    __syncthreads();

    const float kt = key[t];
    int r = 0;
    #pragma unroll 8
    for (int j = 0; j < N_TGT; j++) {
        const float kj = key[j];
        r += (kj > kt) || (kj == kt && j < t);   // stable descending
    }

    #pragma unroll
    for (int k = 0; k < KTOP; k++) {
        const int src = t * KTOP + k;
        const int dst = r * KTOP + k;
        out[dst]        = (float)g_top_idx[src];                  // rows
        out[1024 + dst] = (float)t;                               // cols
        out[2048 + dst] = (g_top_val[src] >= 0.0f) ? 1.0f : 0.0f; // valid
    }
}

// ---------------------------------------------------------------------------
extern "C" void kernel_launch(void* const* d_in, const int* in_sizes, int n_in,
                              void* d_out, int out_size)
{
    const float *th, *xy, *di, *po, *ne, *io, *tg, *W1, *b1, *W2, *b2, *W3, *b3;

    if (n_in >= 13 && in_sizes[0] == 6 * 64) {
        // Alphabetical metadata order
        W1 = (const float*)d_in[0];  W2 = (const float*)d_in[1];
        W3 = (const float*)d_in[2];  b1 = (const float*)d_in[3];
        b2 = (const float*)d_in[4];  b3 = (const float*)d_in[5];
        di = (const float*)d_in[6];  io = (const float*)d_in[7];
        ne = (const float*)d_in[8];  po = (const float*)d_in[9];
        xy = (const float*)d_in[10]; tg = (const float*)d_in[11];
        th = (const float*)d_in[12];
    } else {
        // Insertion (dict) order
        th = (const float*)d_in[0];  xy = (const float*)d_in[1];
        di = (const float*)d_in[2];  po = (const float*)d_in[3];
        ne = (const float*)d_in[4];  io = (const float*)d_in[5];
        tg = (const float*)d_in[6];  W1 = (const float*)d_in[7];
        b1 = (const float*)d_in[8];  W2 = (const float*)d_in[9];
        b2 = (const float*)d_in[10]; W3 = (const float*)d_in[11];
        b3 = (const float*)d_in[12];
    }

    score_mma_kernel<<<4096, 128>>>(th, xy, di, po, ne, io,
                                    W1, b1, W2, b2, W3, b3);
    topk_seg_kernel<<<N_TGT * NSEG, 256>>>();
    topk_merge_kernel<<<N_TGT, 32>>>();
    rescore_kernel<<<N_TGT, 32>>>(th, xy, di, po, ne, io,
                                  W1, b1, W2, b2, W3, b3);
    assemble_kernel<<<1, N_TGT>>>(tg, (float*)d_out);
}

// round 16
// speedup vs baseline: 1.1843x; 1.1843x over previous
#include <cuda_runtime.h>
#include <cuda_bf16.h>

#define N_PROP 65536
#define N_TGT  128
#define KTOP   8
#define KCAND  16

typedef unsigned int u32;

// Scratch (static __device__ — no allocations allowed)
__device__ float g_scoresT[(size_t)N_TGT * N_PROP];   // [T][N] approx keys
__device__ int   g_cand_idx[N_TGT * KCAND];
__device__ float g_top_val[N_TGT * KTOP];
__device__ int   g_top_idx[N_TGT * KTOP];

// pack two f32 -> bf16x2 (lo = second arg)
static __device__ __forceinline__ u32 bfpair(float hi, float lo) {
    u32 d;
    asm("cvt.rn.bf16x2.f32 %0, %1, %2;" : "=r"(d) : "f"(hi), "f"(lo));
    return d;
}

static __device__ __forceinline__ void mma_k8(float c[4], u32 a0, u32 a1, u32 b0) {
    asm volatile(
        "mma.sync.aligned.m16n8k8.row.col.f32.bf16.bf16.f32 "
        "{%0,%1,%2,%3}, {%4,%5}, {%6}, {%0,%1,%2,%3};"
        : "+f"(c[0]), "+f"(c[1]), "+f"(c[2]), "+f"(c[3])
        : "r"(a0), "r"(a1), "r"(b0));
}
static __device__ __forceinline__ void mma_k16(float c[4], const u32 a[4],
                                               u32 b0, u32 b1) {
    asm volatile(
        "mma.sync.aligned.m16n8k16.row.col.f32.bf16.bf16.f32 "
        "{%0,%1,%2,%3}, {%4,%5,%6,%7}, {%8,%9}, {%0,%1,%2,%3};"
        : "+f"(c[0]), "+f"(c[1]), "+f"(c[2]), "+f"(c[3])
        : "r"(a[0]), "r"(a[1]), "r"(a[2]), "r"(a[3]), "r"(b0), "r"(b1));
}

// ---------------------------------------------------------------------------
// Phase A: warp-level HMMA approximate scoring, 2 tiles (32 rows) per warp
// iteration. Rows = flat (n,t): row = n*128 + t. Transposed [T][N] store
// (R14 layout — measured faster than n-major + segmented topk).
// key = logit>=0 ? logit : -1  (approx; exact re-ranking in phase B)
// ---------------------------------------------------------------------------
__global__ __launch_bounds__(128) void score_mma_kernel(
    const float* __restrict__ th, const float* __restrict__ xy,
    const float* __restrict__ di, const float* __restrict__ po,
    const float* __restrict__ ne, const float* __restrict__ io,
    const float* __restrict__ W1, const float* __restrict__ b1,
    const float* __restrict__ W2, const float* __restrict__ b2,
    const float* __restrict__ W3, const float* __restrict__ b3)
{
    const int lane = threadIdx.x & 31;
    const int grp  = lane >> 2;       // 0..7  (row within tile; +8 for upper)
    const int qid  = lane & 3;        // 0..3  (K/N column group)

    const int warps_per_blk = blockDim.x >> 5;
    const int gwarp  = blockIdx.x * warps_per_blk + (threadIdx.x >> 5);
    const int nwarp  = gridDim.x * warps_per_blk;
    const int npairs = (N_PROP * N_TGT) / 32;   // 2 tiles per iteration

    // ---- W1 B-fragments (k8) ----
    u32 bw1[8];
    {
        const int k0 = 2 * qid;
        #pragma unroll
        for (int jt = 0; jt < 8; jt++) {
            const int n = 8 * jt + grp;
            float lo = (k0 == 6) ? b1[n] : W1[k0 * 64 + n];
            float hi = (k0 + 1 == 7) ? 0.0f : W1[(k0 + 1) * 64 + n];
            bw1[jt] = bfpair(hi, lo);
        }
    }

    // ---- W2 B-fragments (k16): [kt][nt] ----
    u32 bw2[4][4][2];
    {
        #pragma unroll
        for (int kt = 0; kt < 4; kt++) {
            const int k0 = 16 * kt + 2 * qid;
            #pragma unroll
            for (int nt = 0; nt < 4; nt++) {
                const int n = 8 * nt + grp;
                bw2[kt][nt][0] = bfpair(W2[(k0 + 1) * 32 + n], W2[k0 * 32 + n]);
                bw2[kt][nt][1] = bfpair(W2[(k0 + 9) * 32 + n], W2[(k0 + 8) * 32 + n]);
            }
        }
    }

    // ---- L3 per-lane constants ----
    float w3v[4][2], b2v[4][2];
    #pragma unroll
    for (int nt = 0; nt < 4; nt++) {
        #pragma unroll
        for (int e = 0; e < 2; e++) {
            const int c = 8 * nt + 2 * qid + e;
            w3v[nt][e] = W3[c];
            b2v[nt][e] = b2[c];
        }
    }
    const float b3v = b3[0];

    // per-lane feature sources: features 2*qid and 2*qid+1
    const float* pA = (qid == 0) ? th : (qid == 1) ? di : ne;   // qid3: dummy
    const float* pB = (qid == 0) ? xy : (qid == 1) ? po : io;
    const float capA = (qid == 0) ? 180.0f : (qid == 1) ? 800.0f : 0.0f;
    const float capB = (qid == 0) ? 800.0f : 0.0f;
    const float invA = (qid == 0) ? (1.0f / 180.0f) : (1.0f / 800.0f);
    const float invB = 1.0f / 800.0f;

    for (int pair = gwarp; pair < npairs; pair += nwarp) {
        const int row0 = pair * 32 + grp;     // tile0: rows row0, row0+8
        const int row1 = row0 + 16;           // tile1: rows row1, row1+8

        // ---- A-fragments for L1 (k8) for both tiles ----
        u32 a0, a1, c0, c1;
        if (qid == 3) {
            a0 = 0x00003F80u; a1 = 0x00003F80u;   // (col6=1.0 bias, col7=0)
            c0 = 0x00003F80u; c1 = 0x00003F80u;
        } else {
            float vA0 = pA[row0],      vB0 = pB[row0];
            float vA8 = pA[row0 + 8],  vB8 = pB[row0 + 8];
            float vC0 = pA[row1],      vD0 = pB[row1];
            float vC8 = pA[row1 + 8],  vD8 = pB[row1 + 8];
            float fA0 = (capA > 0.0f) ? 1.0f - fminf(vA0, capA) * invA : vA0;
            float fA8 = (capA > 0.0f) ? 1.0f - fminf(vA8, capA) * invA : vA8;
            float fC0 = (capA > 0.0f) ? 1.0f - fminf(vC0, capA) * invA : vC0;
            float fC8 = (capA > 0.0f) ? 1.0f - fminf(vC8, capA) * invA : vC8;
            float fB0 = (capB > 0.0f) ? 1.0f - fminf(vB0, capB) * invB : vB0;
            float fB8 = (capB > 0.0f) ? 1.0f - fminf(vB8, capB) * invB : vB8;
            float fD0 = (capB > 0.0f) ? 1.0f - fminf(vD0, capB) * invB : vD0;
            float fD8 = (capB > 0.0f) ? 1.0f - fminf(vD8, capB) * invB : vD8;
            a0 = bfpair(fB0, fA0);
            a1 = bfpair(fB8, fA8);
            c0 = bfpair(fD0, fC0);
            c1 = bfpair(fD8, fC8);
        }

        // ---- L1 tile0 -> compressed A-frags ----
        u32 aF0[4][4], aF1[4][4];
        {
            float h1[8][4];
            #pragma unroll
            for (int jt = 0; jt < 8; jt++) {
                h1[jt][0] = 0.0f; h1[jt][1] = 0.0f; h1[jt][2] = 0.0f; h1[jt][3] = 0.0f;
                mma_k8(h1[jt], a0, a1, bw1[jt]);
            }
            #pragma unroll
            for (int kt = 0; kt < 4; kt++) {
                aF0[kt][0] = bfpair(fmaxf(h1[2*kt][1], 0.0f),   fmaxf(h1[2*kt][0], 0.0f));
                aF0[kt][1] = bfpair(fmaxf(h1[2*kt][3], 0.0f),   fmaxf(h1[2*kt][2], 0.0f));
                aF0[kt][2] = bfpair(fmaxf(h1[2*kt+1][1], 0.0f), fmaxf(h1[2*kt+1][0], 0.0f));
                aF0[kt][3] = bfpair(fmaxf(h1[2*kt+1][3], 0.0f), fmaxf(h1[2*kt+1][2], 0.0f));
            }
        }
        // ---- L1 tile1 ----
        {
            float h1[8][4];
            #pragma unroll
            for (int jt = 0; jt < 8; jt++) {
                h1[jt][0] = 0.0f; h1[jt][1] = 0.0f; h1[jt][2] = 0.0f; h1[jt][3] = 0.0f;
                mma_k8(h1[jt], c0, c1, bw1[jt]);
            }
            #pragma unroll
            for (int kt = 0; kt < 4; kt++) {
                aF1[kt][0] = bfpair(fmaxf(h1[2*kt][1], 0.0f),   fmaxf(h1[2*kt][0], 0.0f));
                aF1[kt][1] = bfpair(fmaxf(h1[2*kt][3], 0.0f),   fmaxf(h1[2*kt][2], 0.0f));
                aF1[kt][2] = bfpair(fmaxf(h1[2*kt+1][1], 0.0f), fmaxf(h1[2*kt+1][0], 0.0f));
                aF1[kt][3] = bfpair(fmaxf(h1[2*kt+1][3], 0.0f), fmaxf(h1[2*kt+1][2], 0.0f));
            }
        }

        // ---- L2: two independent chains, b2 folded into C ----
        float h2a[4][4], h2b[4][4];
        #pragma unroll
        for (int nt = 0; nt < 4; nt++) {
            h2a[nt][0] = b2v[nt][0]; h2a[nt][1] = b2v[nt][1];
            h2a[nt][2] = b2v[nt][0]; h2a[nt][3] = b2v[nt][1];
            h2b[nt][0] = b2v[nt][0]; h2b[nt][1] = b2v[nt][1];
            h2b[nt][2] = b2v[nt][0]; h2b[nt][3] = b2v[nt][1];
        }
        #pragma unroll
        for (int kt = 0; kt < 4; kt++) {
            #pragma unroll
            for (int nt = 0; nt < 4; nt++) {
                mma_k16(h2a[nt], aF0[kt], bw2[kt][nt][0], bw2[kt][nt][1]);
                mma_k16(h2b[nt], aF1[kt], bw2[kt][nt][0], bw2[kt][nt][1]);
            }
        }

        // ---- L3: relu(H2) . W3, quad reduction; two tiles interleaved ----
        float p0 = 0.0f, p8 = 0.0f, q0 = 0.0f, q8 = 0.0f;
        #pragma unroll
        for (int nt = 0; nt < 4; nt++) {
            #pragma unroll
            for (int e = 0; e < 2; e++) {
                p0 = fmaf(fmaxf(h2a[nt][e],     0.0f), w3v[nt][e], p0);
                p8 = fmaf(fmaxf(h2a[nt][2 + e], 0.0f), w3v[nt][e], p8);
                q0 = fmaf(fmaxf(h2b[nt][e],     0.0f), w3v[nt][e], q0);
                q8 = fmaf(fmaxf(h2b[nt][2 + e], 0.0f), w3v[nt][e], q8);
            }
        }
        p0 += __shfl_xor_sync(0xFFFFFFFFu, p0, 1);
        p8 += __shfl_xor_sync(0xFFFFFFFFu, p8, 1);
        q0 += __shfl_xor_sync(0xFFFFFFFFu, q0, 1);
        q8 += __shfl_xor_sync(0xFFFFFFFFu, q8, 1);
        p0 += __shfl_xor_sync(0xFFFFFFFFu, p0, 2);
        p8 += __shfl_xor_sync(0xFFFFFFFFu, p8, 2);
        q0 += __shfl_xor_sync(0xFFFFFFFFu, q0, 2);
        q8 += __shfl_xor_sync(0xFFFFFFFFu, q8, 2);

        if (qid == 0) {
            const float l0 = p0 + b3v, l8 = p8 + b3v;
            const float m0 = q0 + b3v, m8 = q8 + b3v;
            const int r0 = row0, r8 = row0 + 8;
            const int s0 = row1, s8 = row1 + 8;
            g_scoresT[(size_t)(r0 & 127) * N_PROP + (r0 >> 7)] = (l0 >= 0.0f) ? l0 : -1.0f;
            g_scoresT[(size_t)(r8 & 127) * N_PROP + (r8 >> 7)] = (l8 >= 0.0f) ? l8 : -1.0f;
            g_scoresT[(size_t)(s0 & 127) * N_PROP + (s0 >> 7)] = (m0 >= 0.0f) ? m0 : -1.0f;
            g_scoresT[(size_t)(s8 & 127) * N_PROP + (s8 >> 7)] = (m8 >= 0.0f) ? m8 : -1.0f;
        }
    }
}

// ---------------------------------------------------------------------------
// Phase A topk: per-target top-16 candidates (ties -> lowest index).
// ---------------------------------------------------------------------------
__global__ __launch_bounds__(256) void topk16_kernel()
{
    __shared__ float sval[256 * KCAND];
    __shared__ int   sidx[256 * KCAND];

    const int t   = blockIdx.x;
    const int tid = threadIdx.x;
    const float4* __restrict__ col4 = (const float4*)(g_scoresT + (size_t)t * N_PROP);

    float val[KCAND];
    int   idx[KCAND];
    #pragma unroll
    for (int k = 0; k < KCAND; k++) { val[k] = -3.4e38f; idx[k] = 0x7fffffff; }

    for (int q = tid; q < N_PROP / 4; q += 256) {
        const float4 v4 = col4[q];
        const int nb = q * 4;
        float vv[4] = {v4.x, v4.y, v4.z, v4.w};
        #pragma unroll
        for (int u = 0; u < 4; u++) {
            const float v = vv[u];
            if (v > val[KCAND - 1]) {
                val[KCAND - 1] = v; idx[KCAND - 1] = nb + u;
                #pragma unroll
                for (int p = KCAND - 1; p > 0; p--) {
                    if (val[p] > val[p - 1]) {
                        float tv = val[p]; val[p] = val[p - 1]; val[p - 1] = tv;
                        int   ti = idx[p]; idx[p] = idx[p - 1]; idx[p - 1] = ti;
                    }
                }
            }
        }
    }

    #pragma unroll
    for (int k = 0; k < KCAND; k++) { sval[tid * KCAND + k] = val[k]; sidx[tid * KCAND + k] = idx[k]; }
    __syncthreads();

    for (int s = 128; s > 0; s >>= 1) {
        float mv[KCAND]; int mi[KCAND];
        if (tid < s) {
            const float* av = &sval[tid * KCAND];
            const int*   ai = &sidx[tid * KCAND];
            const float* bv = &sval[(tid + s) * KCAND];
            const int*   bi = &sidx[(tid + s) * KCAND];
            int i = 0, j = 0;
            #pragma unroll
            for (int k = 0; k < KCAND; k++) {
                const float va = av[i], vb = bv[j];
                const int   ia = ai[i], ib = bi[j];
                const bool take_a = (va > vb) || (va == vb && ia < ib);
                if (take_a) { mv[k] = va; mi[k] = ia; i++; }
                else        { mv[k] = vb; mi[k] = ib; j++; }
            }
            #pragma unroll
            for (int k = 0; k < KCAND; k++) { sval[tid * KCAND + k] = mv[k]; sidx[tid * KCAND + k] = mi[k]; }
        }
        __syncthreads();
    }

    if (tid == 0) {
        #pragma unroll
        for (int k = 0; k < KCAND; k++)
            g_cand_idx[t * KCAND + k] = sidx[k];
    }
}

// ---------------------------------------------------------------------------
// Phase B: exact fp32 rescoring, one warp per candidate (16 warps per target
// block). Lane l owns hidden units l, l+32 for L1 and output unit l for L2.
// ---------------------------------------------------------------------------
__global__ __launch_bounds__(512) void rescore_kernel(
    const float* __restrict__ th, const float* __restrict__ xy,
    const float* __restrict__ di, const float* __restrict__ po,
    const float* __restrict__ ne, const float* __restrict__ io,
    const float* __restrict__ W1, const float* __restrict__ b1,
    const float* __restrict__ W2, const float* __restrict__ b2,
    const float* __restrict__ W3, const float* __restrict__ b3)
{
    __shared__ float skv[KCAND];
    __shared__ int   ski[KCAND];

    const int t    = blockIdx.x;
    const int wid  = threadIdx.x >> 5;   // candidate 0..15
    const int lane = threadIdx.x & 31;

    const int n   = g_cand_idx[t * KCAND + wid];
    const int off = n * N_TGT + t;

    float f[6];
    f[0] = 1.0f - fminf(th[off], 180.0f) * (1.0f / 180.0f);
    f[1] = 1.0f - fminf(xy[off], 800.0f) * (1.0f / 800.0f);
    f[2] = 1.0f - fminf(di[off], 800.0f) * (1.0f / 800.0f);
    f[3] = po[off];
    f[4] = ne[off];
    f[5] = io[off];

    // L1: lane computes hidden units lane and lane+32
    float ha = b1[lane], hb = b1[lane + 32];
    #pragma unroll
    for (int k = 0; k < 6; k++) {
        ha = fmaf(f[k], W1[k * 64 + lane],      ha);
        hb = fmaf(f[k], W1[k * 64 + lane + 32], hb);
    }
    ha = fmaxf(ha, 0.0f);
    hb = fmaxf(hb, 0.0f);

    // L2: lane owns output unit j = lane; i ascending (matches scalar order)
    float h2 = b2[lane];
    #pragma unroll 8
    for (int i = 0; i < 32; i++) {
        const float hi = __shfl_sync(0xFFFFFFFFu, ha, i);
        h2 = fmaf(hi, W2[i * 32 + lane], h2);
    }
    #pragma unroll 8
    for (int i = 0; i < 32; i++) {
        const float hi = __shfl_sync(0xFFFFFFFFu, hb, i);
        h2 = fmaf(hi, W2[(i + 32) * 32 + lane], h2);
    }

    // L3: relu(h2) * W3[lane], warp tree-reduce
    float p = fmaxf(h2, 0.0f) * W3[lane];
    #pragma unroll
    for (int s = 16; s > 0; s >>= 1)
        p += __shfl_xor_sync(0xFFFFFFFFu, p, s);

    if (lane == 0) {
        const float acc = p + b3[0];
        skv[wid] = (acc >= 0.0f) ? acc : -1.0f;
        ski[wid] = n;
    }
    __syncthreads();

    if (threadIdx.x == 0) {
        bool used[KCAND];
        #pragma unroll
        for (int k = 0; k < KCAND; k++) used[k] = false;
        for (int k = 0; k < KTOP; k++) {
            int best = -1;
            float bv = -3.4e38f; int bi = 0x7fffffff;
            for (int c = 0; c < KCAND; c++) {
                if (used[c]) continue;
                const float v = skv[c]; const int nn = ski[c];
                if (v > bv || (v == bv && nn < bi)) { bv = v; bi = nn; best = c; }
            }
            used[best] = true;
            g_top_val[t * KTOP + k] = bv;
            g_top_idx[t * KTOP + k] = bi;
        }
    }
}

// ---------------------------------------------------------------------------
// Final: stable descending rank of targets[:,1], scatter output as float32.
// out = [rows(1024) | cols(1024) | valid(1024)].
// ---------------------------------------------------------------------------
__global__ __launch_bounds__(N_TGT) void assemble_kernel(
    const float* __restrict__ targets, float* __restrict__ out)
{
    __shared__ float key[N_TGT];
    const int t = threadIdx.x;
    key[t] = targets[t * 4 + 1];
    __syncthreads();

    const float kt = key[t];
    int r = 0;
    #pragma unroll 8
    for (int j = 0; j < N_TGT; j++) {
        const float kj = key[j];
        r += (kj > kt) || (kj == kt && j < t);   // stable descending
    }

    #pragma unroll
    for (int k = 0; k < KTOP; k++) {
        const int src = t * KTOP + k;
        const int dst = r * KTOP + k;
        out[dst]        = (float)g_top_idx[src];                  // rows
        out[1024 + dst] = (float)t;                               // cols
        out[2048 + dst] = (g_top_val[src] >= 0.0f) ? 1.0f : 0.0f; // valid
    }
}

// ---------------------------------------------------------------------------
extern "C" void kernel_launch(void* const* d_in, const int* in_sizes, int n_in,
                              void* d_out, int out_size)
{
    const float *th, *xy, *di, *po, *ne, *io, *tg, *W1, *b1, *W2, *b2, *W3, *b3;

    if (n_in >= 13 && in_sizes[0] == 6 * 64) {
        // Alphabetical metadata order
        W1 = (const float*)d_in[0];  W2 = (const float*)d_in[1];
        W3 = (const float*)d_in[2];  b1 = (const float*)d_in[3];
        b2 = (const float*)d_in[4];  b3 = (const float*)d_in[5];
        di = (const float*)d_in[6];  io = (const float*)d_in[7];
        ne = (const float*)d_in[8];  po = (const float*)d_in[9];
        xy = (const float*)d_in[10]; tg = (const float*)d_in[11];
        th = (const float*)d_in[12];
    } else {
        // Insertion (dict) order
        th = (const float*)d_in[0];  xy = (const float*)d_in[1];
        di = (const float*)d_in[2];  po = (const float*)d_in[3];
        ne = (const float*)d_in[4];  io = (const float*)d_in[5];
        tg = (const float*)d_in[6];  W1 = (const float*)d_in[7];
        b1 = (const float*)d_in[8];  W2 = (const float*)d_in[9];
        b2 = (const float*)d_in[10]; W3 = (const float*)d_in[11];
        b3 = (const float*)d_in[12];
    }

    score_mma_kernel<<<4096, 128>>>(th, xy, di, po, ne, io,
                                    W1, b1, W2, b2, W3, b3);
    topk16_kernel<<<N_TGT, 256>>>();
    rescore_kernel<<<N_TGT, 512>>>(th, xy, di, po, ne, io,
                                   W1, b1, W2, b2, W3, b3);
    assemble_kernel<<<1, N_TGT>>>(tg, (float*)d_out);
}

// round 17
// speedup vs baseline: 1.3543x; 1.1436x over previous
#include <cuda_runtime.h>
#include <cuda_bf16.h>

#define N_PROP 65536
#define N_TGT  128
#define KTOP   8
#define KCAND  16
#define NSEG   4
#define SEGLEN (N_PROP / NSEG)   // 16384

typedef unsigned int u32;

// Scratch (static __device__ — no allocations allowed)
__device__ float g_scoresT[(size_t)N_TGT * N_PROP];   // [T][N] approx keys
__device__ float g_seg_val[N_TGT * NSEG * KCAND];
__device__ int   g_seg_idx[N_TGT * NSEG * KCAND];
__device__ int   g_cand_idx[N_TGT * KCAND];
__device__ float g_top_val[N_TGT * KTOP];
__device__ int   g_top_idx[N_TGT * KTOP];

// pack two f32 -> bf16x2 (lo = second arg)
static __device__ __forceinline__ u32 bfpair(float hi, float lo) {
    u32 d;
    asm("cvt.rn.bf16x2.f32 %0, %1, %2;" : "=r"(d) : "f"(hi), "f"(lo));
    return d;
}

static __device__ __forceinline__ void mma_k8(float c[4], u32 a0, u32 a1, u32 b0) {
    asm volatile(
        "mma.sync.aligned.m16n8k8.row.col.f32.bf16.bf16.f32 "
        "{%0,%1,%2,%3}, {%4,%5}, {%6}, {%0,%1,%2,%3};"
        : "+f"(c[0]), "+f"(c[1]), "+f"(c[2]), "+f"(c[3])
        : "r"(a0), "r"(a1), "r"(b0));
}
static __device__ __forceinline__ void mma_k16(float c[4], const u32 a[4],
                                               u32 b0, u32 b1) {
    asm volatile(
        "mma.sync.aligned.m16n8k16.row.col.f32.bf16.bf16.f32 "
        "{%0,%1,%2,%3}, {%4,%5,%6,%7}, {%8,%9}, {%0,%1,%2,%3};"
        : "+f"(c[0]), "+f"(c[1]), "+f"(c[2]), "+f"(c[3])
        : "r"(a[0]), "r"(a[1]), "r"(a[2]), "r"(a[3]), "r"(b0), "r"(b1));
}

// ---------------------------------------------------------------------------
// Phase A: warp-level HMMA approximate scoring. Each warp owns ONE chunk:
// a fixed 32-target block (tb) x 16 consecutive proposals. Per iteration it
// computes one proposal's 32 targets (2 MMA tiles), parks the 32 scores in
// SMEM; after 16 iterations it flushes a 32t x 16n block with coalesced
// 64-byte row stores (vs 4B stores 256KB apart before).
// key = logit>=0 ? logit : -1  (approx; exact re-ranking in phase B)
// ---------------------------------------------------------------------------
__global__ __launch_bounds__(128) void score_mma_kernel(
    const float* __restrict__ th, const float* __restrict__ xy,
    const float* __restrict__ di, const float* __restrict__ po,
    const float* __restrict__ ne, const float* __restrict__ io,
    const float* __restrict__ W1, const float* __restrict__ b1,
    const float* __restrict__ W2, const float* __restrict__ b2,
    const float* __restrict__ W3, const float* __restrict__ b3)
{
    __shared__ float sbuf[4][32][17];   // [warp][t-offset][n-offset], padded

    const int lane = threadIdx.x & 31;
    const int wrp  = threadIdx.x >> 5;
    const int grp  = lane >> 2;       // 0..7  (row within tile; +8 for upper)
    const int qid  = lane & 3;        // 0..3  (K/N column group)

    const int warps_per_blk = blockDim.x >> 5;
    const int gwarp = blockIdx.x * warps_per_blk + wrp;   // 0..16383, one chunk
    const int tb    = gwarp & 3;                          // t-block 0..3
    const int nblk  = gwarp >> 2;                         // 0..4095
    const int t0    = tb * 32;
    const int n0    = nblk * 16;

    // ---- W1 B-fragments (k8) ----
    u32 bw1[8];
    {
        const int k0 = 2 * qid;
        #pragma unroll
        for (int jt = 0; jt < 8; jt++) {
            const int n = 8 * jt + grp;
            float lo = (k0 == 6) ? b1[n] : W1[k0 * 64 + n];
            float hi = (k0 + 1 == 7) ? 0.0f : W1[(k0 + 1) * 64 + n];
            bw1[jt] = bfpair(hi, lo);
        }
    }

    // ---- W2 B-fragments (k16): [kt][nt] ----
    u32 bw2[4][4][2];
    {
        #pragma unroll
        for (int kt = 0; kt < 4; kt++) {
            const int k0 = 16 * kt + 2 * qid;
            #pragma unroll
            for (int nt = 0; nt < 4; nt++) {
                const int n = 8 * nt + grp;
                bw2[kt][nt][0] = bfpair(W2[(k0 + 1) * 32 + n], W2[k0 * 32 + n]);
                bw2[kt][nt][1] = bfpair(W2[(k0 + 9) * 32 + n], W2[(k0 + 8) * 32 + n]);
            }
        }
    }

    // ---- L3 per-lane constants ----
    float w3v[4][2], b2v[4][2];
    #pragma unroll
    for (int nt = 0; nt < 4; nt++) {
        #pragma unroll
        for (int e = 0; e < 2; e++) {
            const int c = 8 * nt + 2 * qid + e;
            w3v[nt][e] = W3[c];
            b2v[nt][e] = b2[c];
        }
    }
    const float b3v = b3[0];

    // per-lane feature sources: features 2*qid and 2*qid+1
    const float* pA = (qid == 0) ? th : (qid == 1) ? di : ne;   // qid3: dummy
    const float* pB = (qid == 0) ? xy : (qid == 1) ? po : io;
    const float capA = (qid == 0) ? 180.0f : (qid == 1) ? 800.0f : 0.0f;
    const float capB = (qid == 0) ? 800.0f : 0.0f;
    const float invA = (qid == 0) ? (1.0f / 180.0f) : (1.0f / 800.0f);
    const float invB = 1.0f / 800.0f;

    #pragma unroll 1
    for (int i16 = 0; i16 < 16; i16++) {
        const int n    = n0 + i16;
        const int row0 = n * N_TGT + t0 + grp;     // tile0: rows row0, row0+8
        const int row1 = row0 + 16;                // tile1: rows row1, row1+8

        // ---- A-fragments for L1 (k8) for both tiles ----
        u32 a0, a1, c0, c1;
        if (qid == 3) {
            a0 = 0x00003F80u; a1 = 0x00003F80u;   // (col6=1.0 bias, col7=0)
            c0 = 0x00003F80u; c1 = 0x00003F80u;
        } else {
            float vA0 = pA[row0],      vB0 = pB[row0];
            float vA8 = pA[row0 + 8],  vB8 = pB[row0 + 8];
            float vC0 = pA[row1],      vD0 = pB[row1];
            float vC8 = pA[row1 + 8],  vD8 = pB[row1 + 8];
            float fA0 = (capA > 0.0f) ? 1.0f - fminf(vA0, capA) * invA : vA0;
            float fA8 = (capA > 0.0f) ? 1.0f - fminf(vA8, capA) * invA : vA8;
            float fC0 = (capA > 0.0f) ? 1.0f - fminf(vC0, capA) * invA : vC0;
            float fC8 = (capA > 0.0f) ? 1.0f - fminf(vC8, capA) * invA : vC8;
            float fB0 = (capB > 0.0f) ? 1.0f - fminf(vB0, capB) * invB : vB0;
            float fB8 = (capB > 0.0f) ? 1.0f - fminf(vB8, capB) * invB : vB8;
            float fD0 = (capB > 0.0f) ? 1.0f - fminf(vD0, capB) * invB : vD0;
            float fD8 = (capB > 0.0f) ? 1.0f - fminf(vD8, capB) * invB : vD8;
            a0 = bfpair(fB0, fA0);
            a1 = bfpair(fB8, fA8);
            c0 = bfpair(fD0, fC0);
            c1 = bfpair(fD8, fC8);
        }

        // ---- L1 tile0 -> compressed A-frags ----
        u32 aF0[4][4], aF1[4][4];
        {
            float h1[8][4];
            #pragma unroll
            for (int jt = 0; jt < 8; jt++) {
                h1[jt][0] = 0.0f; h1[jt][1] = 0.0f; h1[jt][2] = 0.0f; h1[jt][3] = 0.0f;
                mma_k8(h1[jt], a0, a1, bw1[jt]);
            }
            #pragma unroll
            for (int kt = 0; kt < 4; kt++) {
                aF0[kt][0] = bfpair(fmaxf(h1[2*kt][1], 0.0f),   fmaxf(h1[2*kt][0], 0.0f));
                aF0[kt][1] = bfpair(fmaxf(h1[2*kt][3], 0.0f),   fmaxf(h1[2*kt][2], 0.0f));
                aF0[kt][2] = bfpair(fmaxf(h1[2*kt+1][1], 0.0f), fmaxf(h1[2*kt+1][0], 0.0f));
                aF0[kt][3] = bfpair(fmaxf(h1[2*kt+1][3], 0.0f), fmaxf(h1[2*kt+1][2], 0.0f));
            }
        }
        // ---- L1 tile1 ----
        {
            float h1[8][4];
            #pragma unroll
            for (int jt = 0; jt < 8; jt++) {
                h1[jt][0] = 0.0f; h1[jt][1] = 0.0f; h1[jt][2] = 0.0f; h1[jt][3] = 0.0f;
                mma_k8(h1[jt], c0, c1, bw1[jt]);
            }
            #pragma unroll
            for (int kt = 0; kt < 4; kt++) {
                aF1[kt][0] = bfpair(fmaxf(h1[2*kt][1], 0.0f),   fmaxf(h1[2*kt][0], 0.0f));
                aF1[kt][1] = bfpair(fmaxf(h1[2*kt][3], 0.0f),   fmaxf(h1[2*kt][2], 0.0f));
                aF1[kt][2] = bfpair(fmaxf(h1[2*kt+1][1], 0.0f), fmaxf(h1[2*kt+1][0], 0.0f));
                aF1[kt][3] = bfpair(fmaxf(h1[2*kt+1][3], 0.0f), fmaxf(h1[2*kt+1][2], 0.0f));
            }
        }

        // ---- L2: two independent chains, b2 folded into C ----
        float h2a[4][4], h2b[4][4];
        #pragma unroll
        for (int nt = 0; nt < 4; nt++) {
            h2a[nt][0] = b2v[nt][0]; h2a[nt][1] = b2v[nt][1];
            h2a[nt][2] = b2v[nt][0]; h2a[nt][3] = b2v[nt][1];
            h2b[nt][0] = b2v[nt][0]; h2b[nt][1] = b2v[nt][1];
            h2b[nt][2] = b2v[nt][0]; h2b[nt][3] = b2v[nt][1];
        }
        #pragma unroll
        for (int kt = 0; kt < 4; kt++) {
            #pragma unroll
            for (int nt = 0; nt < 4; nt++) {
                mma_k16(h2a[nt], aF0[kt], bw2[kt][nt][0], bw2[kt][nt][1]);
                mma_k16(h2b[nt], aF1[kt], bw2[kt][nt][0], bw2[kt][nt][1]);
            }
        }

        // ---- L3: relu(H2) . W3, quad reduction; two tiles interleaved ----
        float p0 = 0.0f, p8 = 0.0f, q0 = 0.0f, q8 = 0.0f;
        #pragma unroll
        for (int nt = 0; nt < 4; nt++) {
            #pragma unroll
            for (int e = 0; e < 2; e++) {
                p0 = fmaf(fmaxf(h2a[nt][e],     0.0f), w3v[nt][e], p0);
                p8 = fmaf(fmaxf(h2a[nt][2 + e], 0.0f), w3v[nt][e], p8);
                q0 = fmaf(fmaxf(h2b[nt][e],     0.0f), w3v[nt][e], q0);
                q8 = fmaf(fmaxf(h2b[nt][2 + e], 0.0f), w3v[nt][e], q8);
            }
        }
        p0 += __shfl_xor_sync(0xFFFFFFFFu, p0, 1);
        p8 += __shfl_xor_sync(0xFFFFFFFFu, p8, 1);
        q0 += __shfl_xor_sync(0xFFFFFFFFu, q0, 1);
        q8 += __shfl_xor_sync(0xFFFFFFFFu, q8, 1);
        p0 += __shfl_xor_sync(0xFFFFFFFFu, p0, 2);
        p8 += __shfl_xor_sync(0xFFFFFFFFu, p8, 2);
        q0 += __shfl_xor_sync(0xFFFFFFFFu, q0, 2);
        q8 += __shfl_xor_sync(0xFFFFFFFFu, q8, 2);

        if (qid == 0) {
            const float l0 = p0 + b3v, l8 = p8 + b3v;
            const float m0 = q0 + b3v, m8 = q8 + b3v;
            sbuf[wrp][grp     ][i16] = (l0 >= 0.0f) ? l0 : -1.0f;
            sbuf[wrp][grp +  8][i16] = (l8 >= 0.0f) ? l8 : -1.0f;
            sbuf[wrp][grp + 16][i16] = (m0 >= 0.0f) ? m0 : -1.0f;
            sbuf[wrp][grp + 24][i16] = (m8 >= 0.0f) ? m8 : -1.0f;
        }
    }

    // ---- flush: 32 rows of 16 consecutive n (64B coalesced per row) ----
    __syncwarp();
    if (lane < 16) {
        #pragma unroll 4
        for (int toff = 0; toff < 32; toff++)
            g_scoresT[(size_t)(t0 + toff) * N_PROP + n0 + lane] = sbuf[wrp][toff][lane];
    }
}

// ---------------------------------------------------------------------------
// Topk stage 1: per-(target, segment) top-16 over a CONTIGUOUS 16384-column
// span of the transposed layout (reads stay fully coalesced float4).
// grid = N_TGT * NSEG, 256 threads.
// ---------------------------------------------------------------------------
__global__ __launch_bounds__(256) void topk_seg_kernel()
{
    __shared__ float sval[256 * KCAND];
    __shared__ int   sidx[256 * KCAND];

    const int t    = blockIdx.x >> 2;
    const int seg  = blockIdx.x & (NSEG - 1);
    const int tid  = threadIdx.x;
    const float4* __restrict__ col4 =
        (const float4*)(g_scoresT + (size_t)t * N_PROP + seg * SEGLEN);
    const int nbase = seg * SEGLEN;

    float val[KCAND];
    int   idx[KCAND];
    #pragma unroll
    for (int k = 0; k < KCAND; k++) { val[k] = -3.4e38f; idx[k] = 0x7fffffff; }

    #pragma unroll 2
    for (int q = tid; q < SEGLEN / 4; q += 256) {
        const float4 v4 = col4[q];
        const int nb = nbase + q * 4;
        float vv[4] = {v4.x, v4.y, v4.z, v4.w};
        #pragma unroll
        for (int u = 0; u < 4; u++) {
            const float v = vv[u];
            if (v > val[KCAND - 1]) {
                val[KCAND - 1] = v; idx[KCAND - 1] = nb + u;
                #pragma unroll
                for (int p = KCAND - 1; p > 0; p--) {
                    if (val[p] > val[p - 1]) {
                        float tv = val[p]; val[p] = val[p - 1]; val[p - 1] = tv;
                        int   ti = idx[p]; idx[p] = idx[p - 1]; idx[p - 1] = ti;
                    }
                }
            }
        }
    }

    #pragma unroll
    for (int k = 0; k < KCAND; k++) { sval[tid * KCAND + k] = val[k]; sidx[tid * KCAND + k] = idx[k]; }
    __syncthreads();

    for (int s = 128; s > 0; s >>= 1) {
        float mv[KCAND]; int mi[KCAND];
        if (tid < s) {
            const float* av = &sval[tid * KCAND];
            const int*   ai = &sidx[tid * KCAND];
            const float* bv = &sval[(tid + s) * KCAND];
            const int*   bi = &sidx[(tid + s) * KCAND];
            int i = 0, j = 0;
            #pragma unroll
            for (int k = 0; k < KCAND; k++) {
                const float va = av[i], vb = bv[j];
                const int   ia = ai[i], ib = bi[j];
                const bool take_a = (va > vb) || (va == vb && ia < ib);
                if (take_a) { mv[k] = va; mi[k] = ia; i++; }
                else        { mv[k] = vb; mi[k] = ib; j++; }
            }
            #pragma unroll
            for (int k = 0; k < KCAND; k++) { sval[tid * KCAND + k] = mv[k]; sidx[tid * KCAND + k] = mi[k]; }
        }
        __syncthreads();
    }

    if (tid < KCAND) {
        g_seg_val[(t * NSEG + seg) * KCAND + tid] = sval[tid];
        g_seg_idx[(t * NSEG + seg) * KCAND + tid] = sidx[tid];
    }
}

// ---------------------------------------------------------------------------
// Topk stage 2: merge NSEG sorted 16-lists per target -> top-16 candidates.
// ---------------------------------------------------------------------------
__global__ __launch_bounds__(32) void topk_merge_kernel()
{
    __shared__ float sval[NSEG * KCAND];
    __shared__ int   sidx[NSEG * KCAND];

    const int t   = blockIdx.x;
    const int tid = threadIdx.x;

    for (int x = tid; x < NSEG * KCAND; x += 32) {
        sval[x] = g_seg_val[t * NSEG * KCAND + x];
        sidx[x] = g_seg_idx[t * NSEG * KCAND + x];
    }
    __syncwarp();

    for (int s = NSEG / 2; s > 0; s >>= 1) {
        float mv[KCAND]; int mi[KCAND];
        if (tid < s) {
            const float* av = &sval[tid * KCAND];
            const int*   ai = &sidx[tid * KCAND];
            const float* bv = &sval[(tid + s) * KCAND];
            const int*   bi = &sidx[(tid + s) * KCAND];
            int i = 0, j = 0;
            #pragma unroll
            for (int k = 0; k < KCAND; k++) {
                const float va = av[i], vb = bv[j];
                const int   ia = ai[i], ib = bi[j];
                const bool take_a = (va > vb) || (va == vb && ia < ib);
                if (take_a) { mv[k] = va; mi[k] = ia; i++; }
                else        { mv[k] = vb; mi[k] = ib; j++; }
            }
            #pragma unroll
            for (int k = 0; k < KCAND; k++) { sval[tid * KCAND + k] = mv[k]; sidx[tid * KCAND + k] = mi[k]; }
        }
        __syncwarp();
    }

    if (tid < KCAND)
        g_cand_idx[t * KCAND + tid] = sidx[tid];
}

// ---------------------------------------------------------------------------
// Phase B: exact fp32 rescoring, one warp per candidate (16 warps per target
// block). Lane l owns hidden units l, l+32 for L1 and output unit l for L2.
// ---------------------------------------------------------------------------
__global__ __launch_bounds__(512) void rescore_kernel(
    const float* __restrict__ th, const float* __restrict__ xy,
    const float* __restrict__ di, const float* __restrict__ po,
    const float* __restrict__ ne, const float* __restrict__ io,
    const float* __restrict__ W1, const float* __restrict__ b1,
    const float* __restrict__ W2, const float* __restrict__ b2,
    const float* __restrict__ W3, const float* __restrict__ b3)
{
    __shared__ float skv[KCAND];
    __shared__ int   ski[KCAND];

    const int t    = blockIdx.x;
    const int wid  = threadIdx.x >> 5;   // candidate 0..15
    const int lane = threadIdx.x & 31;

    const int n   = g_cand_idx[t * KCAND + wid];
    const int off = n * N_TGT + t;

    float f[6];
    f[0] = 1.0f - fminf(th[off], 180.0f) * (1.0f / 180.0f);
    f[1] = 1.0f - fminf(xy[off], 800.0f) * (1.0f / 800.0f);
    f[2] = 1.0f - fminf(di[off], 800.0f) * (1.0f / 800.0f);
    f[3] = po[off];
    f[4] = ne[off];
    f[5] = io[off];

    // L1: lane computes hidden units lane and lane+32
    float ha = b1[lane], hb = b1[lane + 32];
    #pragma unroll
    for (int k = 0; k < 6; k++) {
        ha = fmaf(f[k], W1[k * 64 + lane],      ha);
        hb = fmaf(f[k], W1[k * 64 + lane + 32], hb);
    }
    ha = fmaxf(ha, 0.0f);
    hb = fmaxf(hb, 0.0f);

    // L2: lane owns output unit j = lane
    float h2 = b2[lane];
    #pragma unroll 8
    for (int i = 0; i < 32; i++) {
        const float hi = __shfl_sync(0xFFFFFFFFu, ha, i);
        h2 = fmaf(hi, W2[i * 32 + lane], h2);
    }
    #pragma unroll 8
    for (int i = 0; i < 32; i++) {
        const float hi = __shfl_sync(0xFFFFFFFFu, hb, i);
        h2 = fmaf(hi, W2[(i + 32) * 32 + lane], h2);
    }

    // L3: relu(h2) * W3[lane], warp tree-reduce
    float p = fmaxf(h2, 0.0f) * W3[lane];
    #pragma unroll
    for (int s = 16; s > 0; s >>= 1)
        p += __shfl_xor_sync(0xFFFFFFFFu, p, s);

    if (lane == 0) {
        const float acc = p + b3[0];
        skv[wid] = (acc >= 0.0f) ? acc : -1.0f;
        ski[wid] = n;
    }
    __syncthreads();

    if (threadIdx.x == 0) {
        bool used[KCAND];
        #pragma unroll
        for (int k = 0; k < KCAND; k++) used[k] = false;
        for (int k = 0; k < KTOP; k++) {
            int best = -1;
            float bv = -3.4e38f; int bi = 0x7fffffff;
            for (int c = 0; c < KCAND; c++) {
                if (used[c]) continue;
                const float v = skv[c]; const int nn = ski[c];
                if (v > bv || (v == bv && nn < bi)) { bv = v; bi = nn; best = c; }
            }
            used[best] = true;
            g_top_val[t * KTOP + k] = bv;
            g_top_idx[t * KTOP + k] = bi;
        }
    }
}

// ---------------------------------------------------------------------------
// Final: stable descending rank of targets[:,1], scatter output as float32.
// out = [rows(1024) | cols(1024) | valid(1024)].
// ---------------------------------------------------------------------------
__global__ __launch_bounds__(N_TGT) void assemble_kernel(
    const float* __restrict__ targets, float* __restrict__ out)
{
    __shared__ float key[N_TGT];
    const int t = threadIdx.x;
    key[t] = targets[t * 4 + 1];
    __syncthreads();

    const float kt = key[t];
    int r = 0;
    #pragma unroll 8
    for (int j = 0; j < N_TGT; j++) {
        const float kj = key[j];
        r += (kj > kt) || (kj == kt && j < t);   // stable descending
    }

    #pragma unroll
    for (int k = 0; k < KTOP; k++) {
        const int src = t * KTOP + k;
        const int dst = r * KTOP + k;
        out[dst]        = (float)g_top_idx[src];                  // rows
        out[1024 + dst] = (float)t;                               // cols
        out[2048 + dst] = (g_top_val[src] >= 0.0f) ? 1.0f : 0.0f; // valid
    }
}

// ---------------------------------------------------------------------------
extern "C" void kernel_launch(void* const* d_in, const int* in_sizes, int n_in,
                              void* d_out, int out_size)
{
    const float *th, *xy, *di, *po, *ne, *io, *tg, *W1, *b1, *W2, *b2, *W3, *b3;

    if (n_in >= 13 && in_sizes[0] == 6 * 64) {
        // Alphabetical metadata order
        W1 = (const float*)d_in[0];  W2 = (const float*)d_in[1];
        W3 = (const float*)d_in[2];  b1 = (const float*)d_in[3];
        b2 = (const float*)d_in[4];  b3 = (const float*)d_in[5];
        di = (const float*)d_in[6];  io = (const float*)d_in[7];
        ne = (const float*)d_in[8];  po = (const float*)d_in[9];
        xy = (const float*)d_in[10]; tg = (const float*)d_in[11];
        th = (const float*)d_in[12];
    } else {
        // Insertion (dict) order
        th = (const float*)d_in[0];  xy = (const float*)d_in[1];
        di = (const float*)d_in[2];  po = (const float*)d_in[3];
        ne = (const float*)d_in[4];  io = (const float*)d_in[5];
        tg = (const float*)d_in[6];  W1 = (const float*)d_in[7];
        b1 = (const float*)d_in[8];  W2 = (const float*)d_in[9];
        b2 = (const float*)d_in[10]; W3 = (const float*)d_in[11];
        b3 = (const float*)d_in[12];
    }

    score_mma_kernel<<<4096, 128>>>(th, xy, di, po, ne, io,
                                    W1, b1, W2, b2, W3, b3);
    topk_seg_kernel<<<N_TGT * NSEG, 256>>>();
    topk_merge_kernel<<<N_TGT, 32>>>();
    rescore_kernel<<<N_TGT, 512>>>(th, xy, di, po, ne, io,
                                   W1, b1, W2, b2, W3, b3);
    assemble_kernel<<<1, N_TGT>>>(tg, (float*)d_out);
}